// round 1
// baseline (speedup 1.0000x reference)
#include <cuda_runtime.h>
#include <cuda_bf16.h>

// relu(segment_sum(x @ W^T + b))  ==  relu(segment_sum(x) @ W^T + count * b)
// N=500000, H=256, B=1024, seg_ids sorted ascending.

#define H 256
#define B 1024
#define GRID_SS 1480          // segment-sum blocks (~10 per SM)

__device__ float g_pooled[B * H];   // segment sums of x
__device__ float g_count[B];        // nodes per segment (as float)

// ---------------------------------------------------------------------------
// Kernel 1: zero the scratch (graph replays require re-init every launch)
// ---------------------------------------------------------------------------
__global__ void zero_scratch_kernel() {
    int idx = blockIdx.x * blockDim.x + threadIdx.x;
    if (idx < B * H) g_pooled[idx] = 0.0f;
    if (idx < B)     g_count[idx]  = 0.0f;
}

// ---------------------------------------------------------------------------
// Kernel 2: segment-sum of x into g_pooled, run-length counts into g_count.
// 256 threads = 256 columns; each block owns a contiguous row range.
// Fast path: 8-row unrolled (seg sorted -> one boundary check), MLP=8.
// ---------------------------------------------------------------------------
__global__ void __launch_bounds__(H) segsum_kernel(
    const float* __restrict__ x, const int* __restrict__ seg, int N, int rows_per_block)
{
    int r0 = blockIdx.x * rows_per_block;
    int r1 = min(r0 + rows_per_block, N);
    if (r0 >= r1) return;

    const int tid = threadIdx.x;
    float acc = 0.0f;
    int cur = __ldg(&seg[r0]);
    int run_start = r0;

    int r = r0;
    // 8-row unrolled fast path
    for (; r + 8 <= r1; r += 8) {
        // seg sorted: if last row of the group matches cur, all 8 do.
        int s_last = __ldg(&seg[r + 7]);
        if (s_last == cur) {
            float v0 = __ldg(&x[(size_t)(r + 0) * H + tid]);
            float v1 = __ldg(&x[(size_t)(r + 1) * H + tid]);
            float v2 = __ldg(&x[(size_t)(r + 2) * H + tid]);
            float v3 = __ldg(&x[(size_t)(r + 3) * H + tid]);
            float v4 = __ldg(&x[(size_t)(r + 4) * H + tid]);
            float v5 = __ldg(&x[(size_t)(r + 5) * H + tid]);
            float v6 = __ldg(&x[(size_t)(r + 6) * H + tid]);
            float v7 = __ldg(&x[(size_t)(r + 7) * H + tid]);
            acc += ((v0 + v1) + (v2 + v3)) + ((v4 + v5) + (v6 + v7));
        } else {
            // boundary inside this group: handle row-by-row
            #pragma unroll
            for (int k = 0; k < 8; ++k) {
                int rr = r + k;
                int s = __ldg(&seg[rr]);
                if (s != cur) {
                    atomicAdd(&g_pooled[cur * H + tid], acc);
                    if (tid == 0) atomicAdd(&g_count[cur], (float)(rr - run_start));
                    acc = 0.0f; cur = s; run_start = rr;
                }
                acc += __ldg(&x[(size_t)rr * H + tid]);
            }
        }
    }
    // tail rows
    for (; r < r1; ++r) {
        int s = __ldg(&seg[r]);
        if (s != cur) {
            atomicAdd(&g_pooled[cur * H + tid], acc);
            if (tid == 0) atomicAdd(&g_count[cur], (float)(r - run_start));
            acc = 0.0f; cur = s; run_start = r;
        }
        acc += __ldg(&x[(size_t)r * H + tid]);
    }
    // final flush
    atomicAdd(&g_pooled[cur * H + tid], acc);
    if (tid == 0) atomicAdd(&g_count[cur], (float)(r1 - run_start));
}

// ---------------------------------------------------------------------------
// Kernel 3: out[g][j] = relu( sum_k pooled[g][k] * W[j][k] + count[g]*b[j] )
// One block per segment g; thread j computes output column j.
// W rows read as float4; W (256 KB) becomes L2-resident after first wave.
// ---------------------------------------------------------------------------
__global__ void __launch_bounds__(H) finish_kernel(
    const float* __restrict__ W, const float* __restrict__ bias, float* __restrict__ out)
{
    const int g = blockIdx.x;
    const int j = threadIdx.x;

    __shared__ float s[H];
    s[j] = g_pooled[g * H + j];
    __syncthreads();

    float sum = g_count[g] * __ldg(&bias[j]);
    const float4* Wr = reinterpret_cast<const float4*>(W + (size_t)j * H);
    const float4* s4 = reinterpret_cast<const float4*>(s);
    #pragma unroll 8
    for (int k4 = 0; k4 < H / 4; ++k4) {
        float4 w = __ldg(&Wr[k4]);
        float4 sv = s4[k4];
        sum += sv.x * w.x + sv.y * w.y + sv.z * w.z + sv.w * w.w;
    }
    out[g * H + j] = fmaxf(sum, 0.0f);
}

// ---------------------------------------------------------------------------
// Launch
// ---------------------------------------------------------------------------
extern "C" void kernel_launch(void* const* d_in, const int* in_sizes, int n_in,
                              void* d_out, int out_size)
{
    const float* x   = (const float*)d_in[0];   // [N, 256]
    const int*   seg = (const int*)  d_in[1];   // [N]
    const float* W   = (const float*)d_in[2];   // [256, 256]
    const float* b   = (const float*)d_in[3];   // [256]
    float* out = (float*)d_out;                 // [1024, 256]

    const int N = in_sizes[0] / H;

    zero_scratch_kernel<<<(B * H + 1023) / 1024, 1024>>>();

    int rows_per_block = (N + GRID_SS - 1) / GRID_SS;
    segsum_kernel<<<GRID_SS, H>>>(x, seg, N, rows_per_block);

    finish_kernel<<<B, H>>>(W, b, out);
}

// round 2
// speedup vs baseline: 1.7799x; 1.7799x over previous
#include <cuda_runtime.h>
#include <cuda_bf16.h>

// relu(segment_sum(x @ W^T + b))  ==  relu(segment_sum(x) @ W^T + count * b)
// N=500000, H=256, B=1024, seg_ids sorted ascending.

#define H 256
#define HV 64                  // H / 4 (float4 columns)
#define B 1024
#define GRID_SS 1184           // 148 SMs * 8 blocks -> exactly one wave
#define RPI 16                 // rows per iteration (fast path)
#define SEGS_PER_BLK 8         // finish kernel tiling

__device__ float g_pooled[B * H];   // segment sums of x
__device__ float g_count[B];        // nodes per segment (as float)

// ---------------------------------------------------------------------------
// Kernel 1: zero scratch (graph replays require re-init every launch)
// ---------------------------------------------------------------------------
__global__ void zero_scratch_kernel() {
    int idx = blockIdx.x * blockDim.x + threadIdx.x;
    if (idx < (B * H) / 4)
        reinterpret_cast<float4*>(g_pooled)[idx] =
            make_float4(0.f, 0.f, 0.f, 0.f);
    if (idx < B) g_count[idx] = 0.0f;
}

// ---------------------------------------------------------------------------
// Kernel 2: segment-sum of x.
// 256 threads: c = tid&63 -> float4 column group, rowoff = tid>>6 (0..3).
// Each iteration covers 16 rows; thread loads rows r+rowoff+{0,4,8,12}.
// Loads are issued UNCONDITIONALLY (independent of seg) so ptxas keeps MLP=4
// float4 loads (2KB/warp) in flight; the seg check only gates accumulation.
// ---------------------------------------------------------------------------
__device__ __forceinline__ void flush_acc(float4& acc, int cur, int c) {
    float* dst = &g_pooled[cur * H + c * 4];
    atomicAdd(dst + 0, acc.x);
    atomicAdd(dst + 1, acc.y);
    atomicAdd(dst + 2, acc.z);
    atomicAdd(dst + 3, acc.w);
    acc = make_float4(0.f, 0.f, 0.f, 0.f);
}

__global__ void __launch_bounds__(H) segsum_kernel(
    const float* __restrict__ x, const int* __restrict__ seg,
    int N, int rows_per_block)
{
    int r0 = blockIdx.x * rows_per_block;
    int r1 = min(r0 + rows_per_block, N);
    if (r0 >= r1) return;

    const int tid    = threadIdx.x;
    const int c      = tid & 63;     // float4 column group
    const int rowoff = tid >> 6;     // 0..3
    const float4* __restrict__ x4 = reinterpret_cast<const float4*>(x);

    float4 acc = make_float4(0.f, 0.f, 0.f, 0.f);
    int cur       = __ldg(&seg[r0]);
    int run_start = r0;

    int r = r0;
    for (; r + RPI <= r1; r += RPI) {
        // ---- issue ALL loads up front (no control dependence) ----
        size_t base = (size_t)(r + rowoff) * HV + c;
        float4 v0 = __ldg(&x4[base]);
        float4 v1 = __ldg(&x4[base + 4 * HV]);
        float4 v2 = __ldg(&x4[base + 8 * HV]);
        float4 v3 = __ldg(&x4[base + 12 * HV]);
        int s_last = __ldg(&seg[r + RPI - 1]);

        if (s_last == cur) {
            // sorted => all 16 rows belong to cur
            acc.x += (v0.x + v1.x) + (v2.x + v3.x);
            acc.y += (v0.y + v1.y) + (v2.y + v3.y);
            acc.z += (v0.z + v1.z) + (v2.z + v3.z);
            acc.w += (v0.w + v1.w) + (v2.w + v3.w);
        } else {
            // segment boundary inside this group: walk row-by-row.
            float4 vv[4] = {v0, v1, v2, v3};
            #pragma unroll
            for (int k = 0; k < RPI; ++k) {
                int rr = r + k;
                int s = __ldg(&seg[rr]);
                if (s != cur) {
                    flush_acc(acc, cur, c);
                    if (tid == 0)
                        atomicAdd(&g_count[cur], (float)(rr - run_start));
                    cur = s; run_start = rr;
                }
                if ((k & 3) == rowoff) {
                    float4 v = vv[k >> 2];
                    acc.x += v.x; acc.y += v.y; acc.z += v.z; acc.w += v.w;
                }
            }
        }
    }
    // tail rows: rowoff==0 threads carry the data, all threads track flushes
    for (; r < r1; ++r) {
        int s = __ldg(&seg[r]);
        if (s != cur) {
            flush_acc(acc, cur, c);
            if (tid == 0) atomicAdd(&g_count[cur], (float)(r - run_start));
            cur = s; run_start = r;
        }
        if (rowoff == 0) {
            float4 v = __ldg(&x4[(size_t)r * HV + c]);
            acc.x += v.x; acc.y += v.y; acc.z += v.z; acc.w += v.w;
        }
    }
    // final flush
    flush_acc(acc, cur, c);
    if (tid == 0) atomicAdd(&g_count[cur], (float)(r1 - run_start));
}

// ---------------------------------------------------------------------------
// Kernel 3: out[g][j] = relu( pooled[g]·W[j] + count[g]*b[j] )
// 8 segments per block: W[j][k] loaded once, reused for 8 segments.
// W L2 traffic: 128 blocks * 256KB = 32MB (vs 256MB for 1 seg/block).
// ---------------------------------------------------------------------------
__global__ void __launch_bounds__(H) finish_kernel(
    const float* __restrict__ W, const float* __restrict__ bias,
    float* __restrict__ out)
{
    const int g0 = blockIdx.x * SEGS_PER_BLK;
    const int j  = threadIdx.x;

    __shared__ float sp[SEGS_PER_BLK][H];   // 8KB
    {
        float4* d = reinterpret_cast<float4*>(&sp[0][0]);
        const float4* s = reinterpret_cast<const float4*>(&g_pooled[g0 * H]);
        for (int i = j; i < SEGS_PER_BLK * HV; i += H) d[i] = s[i];
    }
    __syncthreads();

    float accs[SEGS_PER_BLK];
    const float bj = __ldg(&bias[j]);
    #pragma unroll
    for (int s = 0; s < SEGS_PER_BLK; ++s)
        accs[s] = g_count[g0 + s] * bj;

    const float4* Wr = reinterpret_cast<const float4*>(W + (size_t)j * H);
    #pragma unroll 4
    for (int k4 = 0; k4 < HV; ++k4) {
        float4 w = __ldg(&Wr[k4]);
        #pragma unroll
        for (int s = 0; s < SEGS_PER_BLK; ++s) {
            float4 p = reinterpret_cast<const float4*>(&sp[s][0])[k4];
            accs[s] += p.x * w.x + p.y * w.y + p.z * w.z + p.w * w.w;
        }
    }
    #pragma unroll
    for (int s = 0; s < SEGS_PER_BLK; ++s)
        out[(g0 + s) * H + j] = fmaxf(accs[s], 0.0f);
}

// ---------------------------------------------------------------------------
// Launch
// ---------------------------------------------------------------------------
extern "C" void kernel_launch(void* const* d_in, const int* in_sizes, int n_in,
                              void* d_out, int out_size)
{
    const float* x   = (const float*)d_in[0];   // [N, 256]
    const int*   seg = (const int*)  d_in[1];   // [N]
    const float* W   = (const float*)d_in[2];   // [256, 256]
    const float* b   = (const float*)d_in[3];   // [256]
    float* out = (float*)d_out;                 // [1024, 256]

    const int N = in_sizes[0] / H;

    zero_scratch_kernel<<<(B * H / 4 + 511) / 512, 512>>>();

    int rows_per_block = (N + GRID_SS - 1) / GRID_SS;
    segsum_kernel<<<GRID_SS, H>>>(x, seg, N, rows_per_block);

    finish_kernel<<<B / SEGS_PER_BLK, H>>>(W, b, out);
}

// round 3
// speedup vs baseline: 1.8594x; 1.0447x over previous
#include <cuda_runtime.h>
#include <cuda_bf16.h>

// relu(segment_sum(x @ W^T + b))  ==  relu(segment_sum(x) @ W^T + count * b)
// N=500000, H=256, B=1024, seg_ids sorted ascending.
//
// Two kernels only. Scratch (g_pooled/g_count) starts zero (CUDA zero-inits
// __device__ globals) and finish_kernel re-zeros exactly the region it
// consumed, so every call -- correctness run and each graph replay -- sees
// zeroed scratch and does identical work.

#define H 256
#define HV 64                  // H / 4 (float4 columns)
#define B 1024
#define TARGET_GRID 1184       // 148 SMs * 8 blocks -> one-wave ceiling
#define RPI 32                 // rows per iteration (fast path), mult of 4
#define SEGS_PER_BLK 16        // finish kernel tiling

__device__ float g_pooled[B * H];   // segment sums of x (starts zeroed)
__device__ float g_count[B];        // nodes per segment (starts zeroed)

// ---------------------------------------------------------------------------
// Kernel 1: segment-sum of x.
// 256 threads: c = tid&63 -> float4 column group, rowoff = tid>>6 (0..3).
// Each iteration covers 32 rows; thread loads rows r+rowoff+{0,4,...,28}
// (8 independent LDG.128 -> 4KB in flight per warp). Loads are issued
// UNCONDITIONALLY; the sorted-seg check only gates how they're accumulated.
// ---------------------------------------------------------------------------
__device__ __forceinline__ void flush_acc(float4& acc, int cur, int c) {
    float* dst = &g_pooled[cur * H + c * 4];
    atomicAdd(dst + 0, acc.x);
    atomicAdd(dst + 1, acc.y);
    atomicAdd(dst + 2, acc.z);
    atomicAdd(dst + 3, acc.w);
    acc = make_float4(0.f, 0.f, 0.f, 0.f);
}

__global__ void __launch_bounds__(H) segsum_kernel(
    const float* __restrict__ x, const int* __restrict__ seg,
    int N, int rows_per_block)
{
    int r0 = blockIdx.x * rows_per_block;
    int r1 = min(r0 + rows_per_block, N);
    if (r0 >= r1) return;

    const int tid    = threadIdx.x;
    const int c      = tid & 63;     // float4 column group
    const int rowoff = tid >> 6;     // 0..3
    const float4* __restrict__ x4 = reinterpret_cast<const float4*>(x);

    float4 acc = make_float4(0.f, 0.f, 0.f, 0.f);
    int cur       = __ldg(&seg[r0]);
    int run_start = r0;

    int r = r0;
    for (; r + RPI <= r1; r += RPI) {
        // ---- issue ALL loads up front (no control dependence) ----
        size_t base = (size_t)(r + rowoff) * HV + c;
        float4 v0 = __ldg(&x4[base + 0 * 4 * HV]);
        float4 v1 = __ldg(&x4[base + 1 * 4 * HV]);
        float4 v2 = __ldg(&x4[base + 2 * 4 * HV]);
        float4 v3 = __ldg(&x4[base + 3 * 4 * HV]);
        float4 v4 = __ldg(&x4[base + 4 * 4 * HV]);
        float4 v5 = __ldg(&x4[base + 5 * 4 * HV]);
        float4 v6 = __ldg(&x4[base + 6 * 4 * HV]);
        float4 v7 = __ldg(&x4[base + 7 * 4 * HV]);
        int s_last = __ldg(&seg[r + RPI - 1]);

        if (s_last == cur) {
            // sorted => all 32 rows belong to cur
            acc.x += ((v0.x + v1.x) + (v2.x + v3.x)) + ((v4.x + v5.x) + (v6.x + v7.x));
            acc.y += ((v0.y + v1.y) + (v2.y + v3.y)) + ((v4.y + v5.y) + (v6.y + v7.y));
            acc.z += ((v0.z + v1.z) + (v2.z + v3.z)) + ((v4.z + v5.z) + (v6.z + v7.z));
            acc.w += ((v0.w + v1.w) + (v2.w + v3.w)) + ((v4.w + v5.w) + (v6.w + v7.w));
        } else {
            // segment boundary inside this group: walk row-by-row.
            float4 vv[8] = {v0, v1, v2, v3, v4, v5, v6, v7};
            #pragma unroll
            for (int k = 0; k < RPI; ++k) {
                int rr = r + k;
                int s = __ldg(&seg[rr]);
                if (s != cur) {
                    flush_acc(acc, cur, c);
                    if (tid == 0)
                        atomicAdd(&g_count[cur], (float)(rr - run_start));
                    cur = s; run_start = rr;
                }
                if ((k & 3) == rowoff) {
                    float4 v = vv[k >> 2];
                    acc.x += v.x; acc.y += v.y; acc.z += v.z; acc.w += v.w;
                }
            }
        }
    }
    // tail rows (only possible in the very last block; usually empty)
    for (; r < r1; ++r) {
        int s = __ldg(&seg[r]);
        if (s != cur) {
            flush_acc(acc, cur, c);
            if (tid == 0) atomicAdd(&g_count[cur], (float)(r - run_start));
            cur = s; run_start = r;
        }
        if (rowoff == 0) {
            float4 v = __ldg(&x4[(size_t)r * HV + c]);
            acc.x += v.x; acc.y += v.y; acc.z += v.z; acc.w += v.w;
        }
    }
    // final flush
    flush_acc(acc, cur, c);
    if (tid == 0) atomicAdd(&g_count[cur], (float)(r1 - run_start));
}

// ---------------------------------------------------------------------------
// Kernel 2: out[g][j] = relu( pooled[g]·W[j] + count[g]*b[j] )
// 16 segments per block: W[j][k] loaded once, reused 16x.
// W L2 traffic: 64 blocks * 256KB = 16MB.
// After consuming its scratch region, the block re-zeros it so the next
// kernel_launch call (graph replay) starts from zeroed scratch.
// ---------------------------------------------------------------------------
__global__ void __launch_bounds__(H) finish_kernel(
    const float* __restrict__ W, const float* __restrict__ bias,
    float* __restrict__ out)
{
    const int g0 = blockIdx.x * SEGS_PER_BLK;
    const int j  = threadIdx.x;

    __shared__ float sp[SEGS_PER_BLK][H];     // 16KB
    __shared__ float scnt[SEGS_PER_BLK];
    {
        float4* d = reinterpret_cast<float4*>(&sp[0][0]);
        float4* s = reinterpret_cast<float4*>(&g_pooled[g0 * H]);
        for (int i = j; i < SEGS_PER_BLK * HV; i += H) d[i] = s[i];
        if (j < SEGS_PER_BLK) scnt[j] = g_count[g0 + j];
    }
    __syncthreads();

    // ---- re-zero the scratch region this block consumed ----
    {
        float4* s = reinterpret_cast<float4*>(&g_pooled[g0 * H]);
        const float4 z = make_float4(0.f, 0.f, 0.f, 0.f);
        for (int i = j; i < SEGS_PER_BLK * HV; i += H) s[i] = z;
        if (j < SEGS_PER_BLK) g_count[g0 + j] = 0.0f;
    }

    float accs[SEGS_PER_BLK];
    const float bj = __ldg(&bias[j]);
    #pragma unroll
    for (int s = 0; s < SEGS_PER_BLK; ++s)
        accs[s] = scnt[s] * bj;

    const float4* Wr = reinterpret_cast<const float4*>(W + (size_t)j * H);
    #pragma unroll 4
    for (int k4 = 0; k4 < HV; ++k4) {
        float4 w = __ldg(&Wr[k4]);
        #pragma unroll
        for (int s = 0; s < SEGS_PER_BLK; ++s) {
            float4 p = reinterpret_cast<const float4*>(&sp[s][0])[k4];
            accs[s] += p.x * w.x + p.y * w.y + p.z * w.z + p.w * w.w;
        }
    }
    #pragma unroll
    for (int s = 0; s < SEGS_PER_BLK; ++s)
        out[(g0 + s) * H + j] = fmaxf(accs[s], 0.0f);
}

// ---------------------------------------------------------------------------
// Launch
// ---------------------------------------------------------------------------
extern "C" void kernel_launch(void* const* d_in, const int* in_sizes, int n_in,
                              void* d_out, int out_size)
{
    const float* x   = (const float*)d_in[0];   // [N, 256]
    const int*   seg = (const int*)  d_in[1];   // [N]
    const float* W   = (const float*)d_in[2];   // [256, 256]
    const float* b   = (const float*)d_in[3];   // [256]
    float* out = (float*)d_out;                 // [1024, 256]

    const int N = in_sizes[0] / H;

    // rows_per_block: multiple of RPI so only the last block can have a tail.
    int rpb = (N + TARGET_GRID - 1) / TARGET_GRID;
    rpb = ((rpb + RPI - 1) / RPI) * RPI;        // N=500000 -> 448
    int grid = (N + rpb - 1) / rpb;             // -> 1117 (single wave)

    segsum_kernel<<<grid, H>>>(x, seg, N, rpb);
    finish_kernel<<<B / SEGS_PER_BLK, H>>>(W, b, out);
}

// round 4
// speedup vs baseline: 1.8883x; 1.0155x over previous
#include <cuda_runtime.h>
#include <cuda_bf16.h>

// relu(segment_sum(x @ W^T + b))  ==  relu(segment_sum(x) @ W^T + count * b)
// N=500000, H=256, B=1024, seg_ids sorted ascending.
//
// Two kernels. Scratch (g_pooled/g_count) starts zero (CUDA zero-inits
// __device__ globals) and finish_kernel re-zeros exactly the region it
// consumed, so every call (correctness run + each graph replay) sees zeroed
// scratch and does identical work.

#define H 256
#define HV 64                  // H / 4 (float4 columns)
#define B 1024
#define TARGET_GRID 1184       // 148 SMs * 8 blocks -> one-wave ceiling
#define RPI 32                 // rows per iteration (fast path), mult of 4
#define SEGS_PER_BLK 4         // finish kernel tiling (grid = 256 blocks)

__device__ float g_pooled[B * H];   // segment sums of x (starts zeroed)
__device__ float g_count[B];        // nodes per segment (starts zeroed)

// ---------------------------------------------------------------------------
// Kernel 1: segment-sum of x.  (measured ~74us = ~6.9 TB/s -- at roofline)
// 256 threads: c = tid&63 -> float4 column group, rowoff = tid>>6 (0..3).
// Each iteration covers 32 rows; thread loads rows r+rowoff+{0,4,...,28}
// (8 independent LDG.128 -> 4KB in flight per warp). Loads are issued
// UNCONDITIONALLY; the sorted-seg check only gates how they're accumulated.
// ---------------------------------------------------------------------------
__device__ __forceinline__ void flush_acc(float4& acc, int cur, int c) {
    float* dst = &g_pooled[cur * H + c * 4];
    atomicAdd(dst + 0, acc.x);
    atomicAdd(dst + 1, acc.y);
    atomicAdd(dst + 2, acc.z);
    atomicAdd(dst + 3, acc.w);
    acc = make_float4(0.f, 0.f, 0.f, 0.f);
}

__global__ void __launch_bounds__(H) segsum_kernel(
    const float* __restrict__ x, const int* __restrict__ seg,
    int N, int rows_per_block)
{
    int r0 = blockIdx.x * rows_per_block;
    int r1 = min(r0 + rows_per_block, N);
    if (r0 >= r1) return;

    const int tid    = threadIdx.x;
    const int c      = tid & 63;     // float4 column group
    const int rowoff = tid >> 6;     // 0..3
    const float4* __restrict__ x4 = reinterpret_cast<const float4*>(x);

    float4 acc = make_float4(0.f, 0.f, 0.f, 0.f);
    int cur       = __ldg(&seg[r0]);
    int run_start = r0;

    int r = r0;
    for (; r + RPI <= r1; r += RPI) {
        // ---- issue ALL loads up front (no control dependence) ----
        size_t base = (size_t)(r + rowoff) * HV + c;
        float4 v0 = __ldg(&x4[base + 0 * 4 * HV]);
        float4 v1 = __ldg(&x4[base + 1 * 4 * HV]);
        float4 v2 = __ldg(&x4[base + 2 * 4 * HV]);
        float4 v3 = __ldg(&x4[base + 3 * 4 * HV]);
        float4 v4 = __ldg(&x4[base + 4 * 4 * HV]);
        float4 v5 = __ldg(&x4[base + 5 * 4 * HV]);
        float4 v6 = __ldg(&x4[base + 6 * 4 * HV]);
        float4 v7 = __ldg(&x4[base + 7 * 4 * HV]);
        int s_last = __ldg(&seg[r + RPI - 1]);

        if (s_last == cur) {
            // sorted => all 32 rows belong to cur
            acc.x += ((v0.x + v1.x) + (v2.x + v3.x)) + ((v4.x + v5.x) + (v6.x + v7.x));
            acc.y += ((v0.y + v1.y) + (v2.y + v3.y)) + ((v4.y + v5.y) + (v6.y + v7.y));
            acc.z += ((v0.z + v1.z) + (v2.z + v3.z)) + ((v4.z + v5.z) + (v6.z + v7.z));
            acc.w += ((v0.w + v1.w) + (v2.w + v3.w)) + ((v4.w + v5.w) + (v6.w + v7.w));
        } else {
            // segment boundary inside this group: walk row-by-row.
            float4 vv[8] = {v0, v1, v2, v3, v4, v5, v6, v7};
            #pragma unroll
            for (int k = 0; k < RPI; ++k) {
                int rr = r + k;
                int s = __ldg(&seg[rr]);
                if (s != cur) {
                    flush_acc(acc, cur, c);
                    if (tid == 0)
                        atomicAdd(&g_count[cur], (float)(rr - run_start));
                    cur = s; run_start = rr;
                }
                if ((k & 3) == rowoff) {
                    float4 v = vv[k >> 2];
                    acc.x += v.x; acc.y += v.y; acc.z += v.z; acc.w += v.w;
                }
            }
        }
    }
    // tail rows (only possible in the very last block; usually empty)
    for (; r < r1; ++r) {
        int s = __ldg(&seg[r]);
        if (s != cur) {
            flush_acc(acc, cur, c);
            if (tid == 0) atomicAdd(&g_count[cur], (float)(r - run_start));
            cur = s; run_start = r;
        }
        if (rowoff == 0) {
            float4 v = __ldg(&x4[(size_t)r * HV + c]);
            acc.x += v.x; acc.y += v.y; acc.z += v.z; acc.w += v.w;
        }
    }
    // final flush
    flush_acc(acc, cur, c);
    if (tid == 0) atomicAdd(&g_count[cur], (float)(r1 - run_start));
}

// ---------------------------------------------------------------------------
// Kernel 2: out[g][j] = relu( pooled[g]·W[j] + count[g]*b[j] )
// 4 segments per block, 256 blocks -> every SM busy (was 64 blocks: 84 SMs
// idle, issue=27.5%). unroll 8 keeps 8 LDG.128 of W in flight to cover L2
// latency. W L2 traffic: 256 * 256KB = 64MB (~6us at LTS throughput).
// smem pooled reads are uniform-address broadcasts (conflict-free).
// After consuming its scratch region, the block re-zeros it so the next
// kernel_launch call (graph replay) starts from zeroed scratch.
// ---------------------------------------------------------------------------
__global__ void __launch_bounds__(H) finish_kernel(
    const float* __restrict__ W, const float* __restrict__ bias,
    float* __restrict__ out)
{
    const int g0 = blockIdx.x * SEGS_PER_BLK;
    const int j  = threadIdx.x;

    __shared__ float sp[SEGS_PER_BLK][H];     // 4KB
    __shared__ float scnt[SEGS_PER_BLK];
    {
        float4* d = reinterpret_cast<float4*>(&sp[0][0]);
        float4* s = reinterpret_cast<float4*>(&g_pooled[g0 * H]);
        for (int i = j; i < SEGS_PER_BLK * HV; i += H) d[i] = s[i];
        if (j < SEGS_PER_BLK) scnt[j] = g_count[g0 + j];
    }
    __syncthreads();

    // ---- re-zero the scratch region this block consumed ----
    {
        float4* s = reinterpret_cast<float4*>(&g_pooled[g0 * H]);
        const float4 z = make_float4(0.f, 0.f, 0.f, 0.f);
        for (int i = j; i < SEGS_PER_BLK * HV; i += H) s[i] = z;
        if (j < SEGS_PER_BLK) g_count[g0 + j] = 0.0f;
    }

    float accs[SEGS_PER_BLK];
    const float bj = __ldg(&bias[j]);
    #pragma unroll
    for (int s = 0; s < SEGS_PER_BLK; ++s)
        accs[s] = scnt[s] * bj;

    const float4* Wr = reinterpret_cast<const float4*>(W + (size_t)j * H);
    #pragma unroll 8
    for (int k4 = 0; k4 < HV; ++k4) {
        float4 w = __ldg(&Wr[k4]);
        #pragma unroll
        for (int s = 0; s < SEGS_PER_BLK; ++s) {
            float4 p = reinterpret_cast<const float4*>(&sp[s][0])[k4];
            accs[s] += p.x * w.x + p.y * w.y + p.z * w.z + p.w * w.w;
        }
    }
    #pragma unroll
    for (int s = 0; s < SEGS_PER_BLK; ++s)
        out[(g0 + s) * H + j] = fmaxf(accs[s], 0.0f);
}

// ---------------------------------------------------------------------------
// Launch
// ---------------------------------------------------------------------------
extern "C" void kernel_launch(void* const* d_in, const int* in_sizes, int n_in,
                              void* d_out, int out_size)
{
    const float* x   = (const float*)d_in[0];   // [N, 256]
    const int*   seg = (const int*)  d_in[1];   // [N]
    const float* W   = (const float*)d_in[2];   // [256, 256]
    const float* b   = (const float*)d_in[3];   // [256]
    float* out = (float*)d_out;                 // [1024, 256]

    const int N = in_sizes[0] / H;

    // rows_per_block: multiple of RPI so only the last block can have a tail.
    int rpb = (N + TARGET_GRID - 1) / TARGET_GRID;
    rpb = ((rpb + RPI - 1) / RPI) * RPI;        // N=500000 -> 448
    int grid = (N + rpb - 1) / rpb;             // -> 1117 (single wave)

    segsum_kernel<<<grid, H>>>(x, seg, N, rpb);
    finish_kernel<<<B / SEGS_PER_BLK, H>>>(W, b, out);
}

// round 5
// speedup vs baseline: 1.9820x; 1.0496x over previous
#include <cuda_runtime.h>
#include <cuda_bf16.h>

// relu(segment_sum(x @ W^T + b))  ==  relu(segment_sum(x) @ W^T + count * b)
// N=500000, H=256, B=1024, seg_ids sorted ascending.

#define H 256
#define HV 64                  // H / 4 (float4 columns)
#define B 1024
#define TARGET_GRID 1184       // segsum: 148 SMs * 8 blocks ceiling
#define RPI 32                 // segsum rows per iteration
#define JT 8                   // finish: j tiles (32 outputs each)
#define ST 32                  // finish: segment tiles (32 segs each)
#define JW 32                  // j per tile
#define SW_PAD 36              // k-major W tile row pitch (floats)

__device__ float g_pooled[B * H];        // segment sums of x (zero-init)
__device__ float g_count[B];             // nodes per segment  (zero-init)
__device__ unsigned int g_done[ST];      // per-seg-tile arrival counters

// ---------------------------------------------------------------------------
// Kernel 1: segment-sum of x.  (~74us = ~6.9 TB/s -- at HBM roofline)
// ---------------------------------------------------------------------------
__device__ __forceinline__ void flush_acc(float4& acc, int cur, int c) {
    float* dst = &g_pooled[cur * H + c * 4];
    atomicAdd(dst + 0, acc.x);
    atomicAdd(dst + 1, acc.y);
    atomicAdd(dst + 2, acc.z);
    atomicAdd(dst + 3, acc.w);
    acc = make_float4(0.f, 0.f, 0.f, 0.f);
}

__global__ void __launch_bounds__(H) segsum_kernel(
    const float* __restrict__ x, const int* __restrict__ seg,
    int N, int rows_per_block)
{
    int r0 = blockIdx.x * rows_per_block;
    int r1 = min(r0 + rows_per_block, N);
    if (r0 >= r1) return;

    const int tid    = threadIdx.x;
    const int c      = tid & 63;
    const int rowoff = tid >> 6;
    const float4* __restrict__ x4 = reinterpret_cast<const float4*>(x);

    float4 acc = make_float4(0.f, 0.f, 0.f, 0.f);
    int cur       = __ldg(&seg[r0]);
    int run_start = r0;

    int r = r0;
    for (; r + RPI <= r1; r += RPI) {
        size_t base = (size_t)(r + rowoff) * HV + c;
        float4 v0 = __ldg(&x4[base + 0 * 4 * HV]);
        float4 v1 = __ldg(&x4[base + 1 * 4 * HV]);
        float4 v2 = __ldg(&x4[base + 2 * 4 * HV]);
        float4 v3 = __ldg(&x4[base + 3 * 4 * HV]);
        float4 v4 = __ldg(&x4[base + 4 * 4 * HV]);
        float4 v5 = __ldg(&x4[base + 5 * 4 * HV]);
        float4 v6 = __ldg(&x4[base + 6 * 4 * HV]);
        float4 v7 = __ldg(&x4[base + 7 * 4 * HV]);
        int s_last = __ldg(&seg[r + RPI - 1]);

        if (s_last == cur) {
            acc.x += ((v0.x + v1.x) + (v2.x + v3.x)) + ((v4.x + v5.x) + (v6.x + v7.x));
            acc.y += ((v0.y + v1.y) + (v2.y + v3.y)) + ((v4.y + v5.y) + (v6.y + v7.y));
            acc.z += ((v0.z + v1.z) + (v2.z + v3.z)) + ((v4.z + v5.z) + (v6.z + v7.z));
            acc.w += ((v0.w + v1.w) + (v2.w + v3.w)) + ((v4.w + v5.w) + (v6.w + v7.w));
        } else {
            float4 vv[8] = {v0, v1, v2, v3, v4, v5, v6, v7};
            #pragma unroll
            for (int k = 0; k < RPI; ++k) {
                int rr = r + k;
                int s = __ldg(&seg[rr]);
                if (s != cur) {
                    flush_acc(acc, cur, c);
                    if (tid == 0)
                        atomicAdd(&g_count[cur], (float)(rr - run_start));
                    cur = s; run_start = rr;
                }
                if ((k & 3) == rowoff) {
                    float4 v = vv[k >> 2];
                    acc.x += v.x; acc.y += v.y; acc.z += v.z; acc.w += v.w;
                }
            }
        }
    }
    for (; r < r1; ++r) {
        int s = __ldg(&seg[r]);
        if (s != cur) {
            flush_acc(acc, cur, c);
            if (tid == 0) atomicAdd(&g_count[cur], (float)(r - run_start));
            cur = s; run_start = r;
        }
        if (rowoff == 0) {
            float4 v = __ldg(&x4[(size_t)r * HV + c]);
            acc.x += v.x; acc.y += v.y; acc.z += v.z; acc.w += v.w;
        }
    }
    flush_acc(acc, cur, c);
    if (tid == 0) atomicAdd(&g_count[cur], (float)(r1 - run_start));
}

// ---------------------------------------------------------------------------
// Kernel 2: tiled epilogue GEMM.
// Block (jt, st): out[g0..g0+32)[j0..j0+32) = relu(pooled·W^T + count*b).
// W tile (32 rows, 32KB) staged COALESCED into smem transposed to k-major
// sw[k][j] (pad 36) -> compute reads are conflict-free LDS.128.
// (Previous version read W rows directly: 32 L1 wavefronts per LDG -> 25us.)
// pooled is read from L2 as broadcast float4 LDGs.
// Last of the 8 j-tile blocks per seg-tile re-zeros that scratch region.
// ---------------------------------------------------------------------------
__global__ void __launch_bounds__(256) finish_kernel(
    const float* __restrict__ W, const float* __restrict__ bias,
    float* __restrict__ out)
{
    const int jt = blockIdx.x & (JT - 1);
    const int st = blockIdx.x >> 3;
    const int j0 = jt * JW;
    const int g0 = st * 32;
    const int t  = threadIdx.x;

    __shared__ __align__(16) float sw[256 * SW_PAD];   // 36KB, k-major
    __shared__ int s_last_flag;

    // ---- stage W[j0..j0+32)[0..256) transposed: sw[k*36 + jj] = W[j0+jj][k]
    // LDG.128 coalesced (4 lines/warp-instr); STS scalar (4-way conflict, cheap)
    {
        const int jj = t >> 3;          // 0..31 (row within tile)
        const int kb = t & 7;           // float4 group base
        const float4* wr = reinterpret_cast<const float4*>(W + (size_t)(j0 + jj) * H);
        #pragma unroll
        for (int kc = 0; kc < 8; ++kc) {
            int k4 = kb + kc * 8;       // 0..63
            float4 v = __ldg(&wr[k4]);
            int k = k4 * 4;
            sw[(k + 0) * SW_PAD + jj] = v.x;
            sw[(k + 1) * SW_PAD + jj] = v.y;
            sw[(k + 2) * SW_PAD + jj] = v.z;
            sw[(k + 3) * SW_PAD + jj] = v.w;
        }
    }
    __syncthreads();

    // ---- compute: thread = (j4 = t&7 -> 4 consecutive j, s = t>>3 -> 1 seg)
    const int j4 = t & 7;
    const int s  = t >> 3;
    const int g  = g0 + s;

    const float4* p4 = reinterpret_cast<const float4*>(g_pooled) + (size_t)g * HV;
    const float  cnt = __ldg(&g_count[g]);
    const float4 b4  = __ldg(reinterpret_cast<const float4*>(bias) + jt * 8 + j4);
    float4 acc = make_float4(cnt * b4.x, cnt * b4.y, cnt * b4.z, cnt * b4.w);

    #pragma unroll 8
    for (int k4 = 0; k4 < HV; ++k4) {
        float4 p = __ldg(&p4[k4]);
        const float* swk = &sw[(k4 * 4) * SW_PAD + j4 * 4];
        float4 w0 = *reinterpret_cast<const float4*>(swk + 0 * SW_PAD);
        float4 w1 = *reinterpret_cast<const float4*>(swk + 1 * SW_PAD);
        float4 w2 = *reinterpret_cast<const float4*>(swk + 2 * SW_PAD);
        float4 w3 = *reinterpret_cast<const float4*>(swk + 3 * SW_PAD);
        acc.x += w0.x * p.x + w1.x * p.y + w2.x * p.z + w3.x * p.w;
        acc.y += w0.y * p.x + w1.y * p.y + w2.y * p.z + w3.y * p.w;
        acc.z += w0.z * p.x + w1.z * p.y + w2.z * p.z + w3.z * p.w;
        acc.w += w0.w * p.x + w1.w * p.y + w2.w * p.z + w3.w * p.w;
    }

    float4 o = make_float4(fmaxf(acc.x, 0.f), fmaxf(acc.y, 0.f),
                           fmaxf(acc.z, 0.f), fmaxf(acc.w, 0.f));
    reinterpret_cast<float4*>(out)[(size_t)g * HV + jt * 8 + j4] = o;

    // ---- last j-tile block for this seg-tile re-zeros the scratch region
    __syncthreads();           // all threads' pooled reads complete (consumed)
    if (t == 0) {
        __threadfence();
        s_last_flag = (atomicAdd(&g_done[st], 1u) == JT - 1) ? 1 : 0;
    }
    __syncthreads();
    if (s_last_flag) {
        float4 z = make_float4(0.f, 0.f, 0.f, 0.f);
        float4* pz = reinterpret_cast<float4*>(g_pooled) + (size_t)g0 * HV;
        for (int i = t; i < 32 * HV; i += 256) pz[i] = z;
        if (t < 32) g_count[g0 + t] = 0.f;
        if (t == 0) g_done[st] = 0u;
    }
}

// ---------------------------------------------------------------------------
// Launch
// ---------------------------------------------------------------------------
extern "C" void kernel_launch(void* const* d_in, const int* in_sizes, int n_in,
                              void* d_out, int out_size)
{
    const float* x   = (const float*)d_in[0];   // [N, 256]
    const int*   seg = (const int*)  d_in[1];   // [N]
    const float* W   = (const float*)d_in[2];   // [256, 256]
    const float* b   = (const float*)d_in[3];   // [256]
    float* out = (float*)d_out;                 // [1024, 256]

    const int N = in_sizes[0] / H;

    int rpb = (N + TARGET_GRID - 1) / TARGET_GRID;
    rpb = ((rpb + RPI - 1) / RPI) * RPI;        // N=500000 -> 448
    int grid = (N + rpb - 1) / rpb;             // -> 1117 (single wave)

    segsum_kernel<<<grid, H>>>(x, seg, N, rpb);
    finish_kernel<<<JT * ST, 256>>>(W, b, out);
}

// round 6
// speedup vs baseline: 2.0061x; 1.0121x over previous
#include <cuda_runtime.h>
#include <cuda_bf16.h>

// relu(segment_sum(x @ W^T + b))  ==  relu(segment_sum(x) @ W^T + count * b)
// N=500000, H=256, B=1024, seg_ids sorted ascending.

#define H 256
#define HV 64                  // H / 4 (float4 columns)
#define B 1024
#define TARGET_GRID 1184       // segsum: 148 SMs * 8 blocks ceiling
#define RPI 32                 // segsum rows per iteration
#define JT 8                   // finish: j tiles (32 outputs each)
#define ST 32                  // finish: segment tiles (32 segs each)
#define JW 32                  // j per tile
#define SW_PAD 36              // k-major W tile row pitch (floats)
#define FIN_THREADS 512        // 2-way k-split -> 2x occupancy vs 256

__device__ float g_pooled[B * H];        // segment sums of x (zero-init)
__device__ float g_count[B];             // nodes per segment  (zero-init)
__device__ unsigned int g_done[ST];      // per-seg-tile arrival counters

// ---------------------------------------------------------------------------
// Kernel 1: segment-sum of x.  (~74us = ~6.9 TB/s -- at HBM roofline)
// ---------------------------------------------------------------------------
__device__ __forceinline__ void flush_acc(float4& acc, int cur, int c) {
    float* dst = &g_pooled[cur * H + c * 4];
    atomicAdd(dst + 0, acc.x);
    atomicAdd(dst + 1, acc.y);
    atomicAdd(dst + 2, acc.z);
    atomicAdd(dst + 3, acc.w);
    acc = make_float4(0.f, 0.f, 0.f, 0.f);
}

__global__ void __launch_bounds__(H) segsum_kernel(
    const float* __restrict__ x, const int* __restrict__ seg,
    int N, int rows_per_block)
{
    int r0 = blockIdx.x * rows_per_block;
    int r1 = min(r0 + rows_per_block, N);
    if (r0 >= r1) return;

    const int tid    = threadIdx.x;
    const int c      = tid & 63;
    const int rowoff = tid >> 6;
    const float4* __restrict__ x4 = reinterpret_cast<const float4*>(x);

    float4 acc = make_float4(0.f, 0.f, 0.f, 0.f);
    int cur       = __ldg(&seg[r0]);
    int run_start = r0;

    int r = r0;
    for (; r + RPI <= r1; r += RPI) {
        size_t base = (size_t)(r + rowoff) * HV + c;
        float4 v0 = __ldg(&x4[base + 0 * 4 * HV]);
        float4 v1 = __ldg(&x4[base + 1 * 4 * HV]);
        float4 v2 = __ldg(&x4[base + 2 * 4 * HV]);
        float4 v3 = __ldg(&x4[base + 3 * 4 * HV]);
        float4 v4 = __ldg(&x4[base + 4 * 4 * HV]);
        float4 v5 = __ldg(&x4[base + 5 * 4 * HV]);
        float4 v6 = __ldg(&x4[base + 6 * 4 * HV]);
        float4 v7 = __ldg(&x4[base + 7 * 4 * HV]);
        int s_last = __ldg(&seg[r + RPI - 1]);

        if (s_last == cur) {
            acc.x += ((v0.x + v1.x) + (v2.x + v3.x)) + ((v4.x + v5.x) + (v6.x + v7.x));
            acc.y += ((v0.y + v1.y) + (v2.y + v3.y)) + ((v4.y + v5.y) + (v6.y + v7.y));
            acc.z += ((v0.z + v1.z) + (v2.z + v3.z)) + ((v4.z + v5.z) + (v6.z + v7.z));
            acc.w += ((v0.w + v1.w) + (v2.w + v3.w)) + ((v4.w + v5.w) + (v6.w + v7.w));
        } else {
            float4 vv[8] = {v0, v1, v2, v3, v4, v5, v6, v7};
            #pragma unroll
            for (int k = 0; k < RPI; ++k) {
                int rr = r + k;
                int s = __ldg(&seg[rr]);
                if (s != cur) {
                    flush_acc(acc, cur, c);
                    if (tid == 0)
                        atomicAdd(&g_count[cur], (float)(rr - run_start));
                    cur = s; run_start = rr;
                }
                if ((k & 3) == rowoff) {
                    float4 v = vv[k >> 2];
                    acc.x += v.x; acc.y += v.y; acc.z += v.z; acc.w += v.w;
                }
            }
        }
    }
    for (; r < r1; ++r) {
        int s = __ldg(&seg[r]);
        if (s != cur) {
            flush_acc(acc, cur, c);
            if (tid == 0) atomicAdd(&g_count[cur], (float)(r - run_start));
            cur = s; run_start = r;
        }
        if (rowoff == 0) {
            float4 v = __ldg(&x4[(size_t)r * HV + c]);
            acc.x += v.x; acc.y += v.y; acc.z += v.z; acc.w += v.w;
        }
    }
    flush_acc(acc, cur, c);
    if (tid == 0) atomicAdd(&g_count[cur], (float)(r1 - run_start));
}

// ---------------------------------------------------------------------------
// Kernel 2: tiled epilogue GEMM with 2-way k-split.
// Block (jt, st): out[g0..g0+32)[j0..j0+32).
// 512 threads: (j4 = t&7 -> 4 consecutive j, s = (t>>3)&31, kh = t>>8).
// Thread kh computes the partial dot over k4 in [kh*32, kh*32+32); kh=1
// partials are reduced into kh=0 through a 4KB smem buffer.
// W tile staged coalesced + transposed to k-major (conflict-aware pad 36).
// Last of the 8 j-tile blocks per seg-tile re-zeros that scratch region.
// ---------------------------------------------------------------------------
__global__ void __launch_bounds__(FIN_THREADS) finish_kernel(
    const float* __restrict__ W, const float* __restrict__ bias,
    float* __restrict__ out)
{
    const int jt = blockIdx.x & (JT - 1);
    const int st = blockIdx.x >> 3;
    const int j0 = jt * JW;
    const int g0 = st * 32;
    const int t  = threadIdx.x;

    __shared__ __align__(16) float sw[256 * SW_PAD];      // 36.9KB, k-major
    __shared__ __align__(16) float4 sred[32 * 8];         // 4KB partials
    __shared__ int s_last_flag;

    // ---- stage W[j0..j0+32)[0..256) transposed: sw[k*36 + jj] = W[j0+jj][k]
    // 512 threads: jj = t>>4 (row in tile), kb = t&15; 4 chunks each.
    {
        const int jj = t >> 4;          // 0..31
        const int kb = t & 15;          // 0..15
        const float4* wr = reinterpret_cast<const float4*>(W + (size_t)(j0 + jj) * H);
        #pragma unroll
        for (int kc = 0; kc < 4; ++kc) {
            int k4 = kb + kc * 16;      // 0..63
            float4 v = __ldg(&wr[k4]);
            int k = k4 * 4;
            sw[(k + 0) * SW_PAD + jj] = v.x;
            sw[(k + 1) * SW_PAD + jj] = v.y;
            sw[(k + 2) * SW_PAD + jj] = v.z;
            sw[(k + 3) * SW_PAD + jj] = v.w;
        }
    }
    __syncthreads();

    // ---- compute partial dot over this thread's k half ----
    const int j4 = t & 7;
    const int s  = (t >> 3) & 31;
    const int kh = t >> 8;              // 0 or 1
    const int g  = g0 + s;

    const float4* p4 = reinterpret_cast<const float4*>(g_pooled) + (size_t)g * HV;

    float4 acc = make_float4(0.f, 0.f, 0.f, 0.f);
    if (kh == 0) {
        const float cnt = __ldg(&g_count[g]);
        const float4 b4 = __ldg(reinterpret_cast<const float4*>(bias) + jt * 8 + j4);
        acc = make_float4(cnt * b4.x, cnt * b4.y, cnt * b4.z, cnt * b4.w);
    }

    const int k4_0 = kh * 32;
    #pragma unroll 8
    for (int kk = 0; kk < 32; ++kk) {
        int k4 = k4_0 + kk;
        float4 p = __ldg(&p4[k4]);
        const float* swk = &sw[(k4 * 4) * SW_PAD + j4 * 4];
        float4 w0 = *reinterpret_cast<const float4*>(swk + 0 * SW_PAD);
        float4 w1 = *reinterpret_cast<const float4*>(swk + 1 * SW_PAD);
        float4 w2 = *reinterpret_cast<const float4*>(swk + 2 * SW_PAD);
        float4 w3 = *reinterpret_cast<const float4*>(swk + 3 * SW_PAD);
        acc.x += w0.x * p.x + w1.x * p.y + w2.x * p.z + w3.x * p.w;
        acc.y += w0.y * p.x + w1.y * p.y + w2.y * p.z + w3.y * p.w;
        acc.z += w0.z * p.x + w1.z * p.y + w2.z * p.z + w3.z * p.w;
        acc.w += w0.w * p.x + w1.w * p.y + w2.w * p.z + w3.w * p.w;
    }

    // ---- reduce kh=1 partial into kh=0, apply relu, store ----
    if (kh == 1) sred[s * 8 + j4] = acc;
    __syncthreads();
    if (kh == 0) {
        float4 r = sred[s * 8 + j4];
        acc.x += r.x; acc.y += r.y; acc.z += r.z; acc.w += r.w;
        float4 o = make_float4(fmaxf(acc.x, 0.f), fmaxf(acc.y, 0.f),
                               fmaxf(acc.z, 0.f), fmaxf(acc.w, 0.f));
        reinterpret_cast<float4*>(out)[(size_t)g * HV + jt * 8 + j4] = o;
    }

    // ---- last j-tile block for this seg-tile re-zeros the scratch region
    __syncthreads();           // all pooled reads complete (consumed)
    if (t == 0) {
        __threadfence();
        s_last_flag = (atomicAdd(&g_done[st], 1u) == JT - 1) ? 1 : 0;
    }
    __syncthreads();
    if (s_last_flag) {
        float4 z = make_float4(0.f, 0.f, 0.f, 0.f);
        float4* pz = reinterpret_cast<float4*>(g_pooled) + (size_t)g0 * HV;
        for (int i = t; i < 32 * HV; i += FIN_THREADS) pz[i] = z;
        if (t < 32) g_count[g0 + t] = 0.f;
        if (t == 0) g_done[st] = 0u;
    }
}

// ---------------------------------------------------------------------------
// Launch
// ---------------------------------------------------------------------------
extern "C" void kernel_launch(void* const* d_in, const int* in_sizes, int n_in,
                              void* d_out, int out_size)
{
    const float* x   = (const float*)d_in[0];   // [N, 256]
    const int*   seg = (const int*)  d_in[1];   // [N]
    const float* W   = (const float*)d_in[2];   // [256, 256]
    const float* b   = (const float*)d_in[3];   // [256]
    float* out = (float*)d_out;                 // [1024, 256]

    const int N = in_sizes[0] / H;

    int rpb = (N + TARGET_GRID - 1) / TARGET_GRID;
    rpb = ((rpb + RPI - 1) / RPI) * RPI;        // N=500000 -> 448
    int grid = (N + rpb - 1) / rpb;             // -> 1117 (single wave)

    segsum_kernel<<<grid, H>>>(x, seg, N, rpb);
    finish_kernel<<<JT * ST, FIN_THREADS>>>(W, b, out);
}